// round 1
// baseline (speedup 1.0000x reference)
#include <cuda_runtime.h>
#include <cstddef>

// ---------------- problem constants ----------------
constexpr int BWIN = 4096;       // windows (batch)
constexpr int NTOK = 64;         // tokens per window
constexpr int CDIM = 256;        // channels
constexpr int HEADS = 8;
constexpr int DHEAD = 32;
constexpr int MROWS = BWIN * NTOK;         // 262144
constexpr float SCALE = 0.1767766952966369f; // 32^-0.5

// ---------------- scratch (static device, no allocs) ----------------
__device__ float g_q[BWIN * HEADS * NTOK * DHEAD]; // [b,h,n,d], pre-scaled
__device__ float g_k[BWIN * HEADS * NTOK * DHEAD];
__device__ float g_v[BWIN * HEADS * NTOK * DHEAD];
__device__ float g_o[MROWS * CDIM];                // [m, h*32+d]

// ---------------- GEMM: out[m,c] = A[m,:] . W[c,:] + b[c] ----------------
// MODE 0: A = x, columns 0..255 from Wq/bq -> g_q (scaled), 256..511 -> g_k, 512..767 -> g_v
// MODE 1: A = g_o, W = Wp/bp -> outP[m*256+c]
template <int MODE>
__global__ void __launch_bounds__(256) gemm_kernel(
    const float* __restrict__ A_in,
    const float* __restrict__ W0, const float* __restrict__ b0,
    const float* __restrict__ W1, const float* __restrict__ b1,
    float* __restrict__ outP)
{
    constexpr int BM = 128, BN = 64, BK = 16;
    __shared__ float As[BK][BM];
    __shared__ float Bs[BK][BN];

    const float* A = (MODE == 0) ? A_in : g_o;

    const int m0 = blockIdx.x * BM;
    const int c0 = blockIdx.y * BN;

    const float* Wsrc;
    const float* bsrc;
    int crow0;
    if (MODE == 1) {
        Wsrc = W0; bsrc = b0; crow0 = c0;
    } else {
        if (c0 < 256) { Wsrc = W0; bsrc = b0; crow0 = c0; }
        else          { Wsrc = W1; bsrc = b1; crow0 = c0 - 256; }
    }

    const int t = threadIdx.x;
    const int rowg = t >> 4;   // 0..15 -> 8 rows each
    const int colg = t & 15;   // 0..15 -> 4 cols each

    float acc[8][4];
#pragma unroll
    for (int i = 0; i < 8; i++)
#pragma unroll
        for (int c = 0; c < 4; c++) acc[i][c] = 0.f;

    for (int k0 = 0; k0 < CDIM; k0 += BK) {
        // A tile: 128 x 16 (transposed store)
#pragma unroll
        for (int it = 0; it < 2; it++) {
            int idx = t + it * 256;          // 0..511
            int row = idx >> 2;              // 0..127
            int jc  = (idx & 3) << 2;        // 0,4,8,12
            float4 va = *(const float4*)(A + (size_t)(m0 + row) * CDIM + k0 + jc);
            As[jc + 0][row] = va.x;
            As[jc + 1][row] = va.y;
            As[jc + 2][row] = va.z;
            As[jc + 3][row] = va.w;
        }
        // B tile: 64 x 16 (transposed store)
        {
            int i  = t >> 2;                 // 0..63
            int jc = (t & 3) << 2;
            float4 vb = *(const float4*)(Wsrc + (size_t)(crow0 + i) * CDIM + k0 + jc);
            Bs[jc + 0][i] = vb.x;
            Bs[jc + 1][i] = vb.y;
            Bs[jc + 2][i] = vb.z;
            Bs[jc + 3][i] = vb.w;
        }
        __syncthreads();

#pragma unroll
        for (int j = 0; j < BK; j++) {
            float a[8], bb[4];
            *(float4*)&a[0] = *(const float4*)&As[j][rowg * 8];
            *(float4*)&a[4] = *(const float4*)&As[j][rowg * 8 + 4];
            *(float4*)&bb[0] = *(const float4*)&Bs[j][colg * 4];
#pragma unroll
            for (int i = 0; i < 8; i++)
#pragma unroll
                for (int c = 0; c < 4; c++)
                    acc[i][c] = fmaf(a[i], bb[c], acc[i][c]);
        }
        __syncthreads();
    }

    // epilogue
    float bias[4];
#pragma unroll
    for (int c = 0; c < 4; c++) bias[c] = bsrc[crow0 + colg * 4 + c];

#pragma unroll
    for (int i = 0; i < 8; i++) {
        int m = m0 + rowg * 8 + i;
        int b = m >> 6, n = m & 63;
#pragma unroll
        for (int c = 0; c < 4; c++) {
            int cg = c0 + colg * 4 + c;
            float val = acc[i][c] + bias[c];
            if (MODE == 1) {
                outP[(size_t)m * CDIM + cg] = val;
            } else {
                if (cg < 256) {
                    int hh = cg >> 5, dd = cg & 31;
                    g_q[(((size_t)(b * 8 + hh)) * 64 + n) * 32 + dd] = val * SCALE;
                } else if (cg < 512) {
                    int c2 = cg - 256;
                    int hh = c2 >> 5, dd = c2 & 31;
                    g_k[(((size_t)(b * 8 + hh)) * 64 + n) * 32 + dd] = val;
                } else {
                    int c2 = cg - 512;
                    int hh = c2 >> 5, dd = c2 & 31;
                    g_v[(((size_t)(b * 8 + hh)) * 64 + n) * 32 + dd] = val;
                }
            }
        }
    }
}

// ---------------- fused attention per (window, head) ----------------
__global__ void __launch_bounds__(256) attn_kernel(
    const float* __restrict__ mask,
    const float* __restrict__ bias_table)
{
    const int bh = blockIdx.x;      // 0..32767
    const int b  = bh >> 3;
    const int h  = bh & 7;

    __shared__ float qs_t[32 * 64];     // [d][n]  (transposed)
    __shared__ float ks_t[32 * 64];     // [d][n]
    __shared__ float vs[64 * 32];       // [n][d]
    __shared__ float S[64 * 65];        // stride 65 (conflict-free)
    __shared__ float rowmax[64];
    __shared__ float rowinv[64];

    const int t = threadIdx.x;
    const float* qg = g_q + (size_t)bh * 2048;
    const float* kg = g_k + (size_t)bh * 2048;
    const float* vg = g_v + (size_t)bh * 2048;

    // load tiles; q/k transposed into [d][n]
#pragma unroll
    for (int it = 0; it < 2; it++) {
        int e = (t + it * 256) * 4;    // 0..2044, step 4
        int n = e >> 5;
        int d = e & 31;
        float4 vq = *(const float4*)&qg[e];
        float4 vk = *(const float4*)&kg[e];
        float4 vv = *(const float4*)&vg[e];
        qs_t[(d + 0) * 64 + n] = vq.x;
        qs_t[(d + 1) * 64 + n] = vq.y;
        qs_t[(d + 2) * 64 + n] = vq.z;
        qs_t[(d + 3) * 64 + n] = vq.w;
        ks_t[(d + 0) * 64 + n] = vk.x;
        ks_t[(d + 1) * 64 + n] = vk.y;
        ks_t[(d + 2) * 64 + n] = vk.z;
        ks_t[(d + 3) * 64 + n] = vk.w;
        *(float4*)&vs[e] = vv;
    }
    __syncthreads();

    // S = (q*scale) . k^T : thread handles a 4x4 tile
    const int i0 = (t >> 4) << 2;  // 0,4,...,60
    const int j0 = (t & 15) << 2;  // 0,4,...,60
    float s[4][4];
#pragma unroll
    for (int i = 0; i < 4; i++)
#pragma unroll
        for (int j = 0; j < 4; j++) s[i][j] = 0.f;

#pragma unroll
    for (int d = 0; d < 32; d++) {
        float qr[4], kr[4];
        *(float4*)qr = *(const float4*)&qs_t[d * 64 + i0];
        *(float4*)kr = *(const float4*)&ks_t[d * 64 + j0];
#pragma unroll
        for (int i = 0; i < 4; i++)
#pragma unroll
            for (int j = 0; j < 4; j++)
                s[i][j] = fmaf(qr[i], kr[j], s[i][j]);
    }

    // add relative-position bias + shift mask
    const int w = b & 1023;
    const float* mrow = mask + (size_t)w * 4096;
#pragma unroll
    for (int i = 0; i < 4; i++) {
        int ii = i0 + i;
        int ih = ii >> 3, iw = ii & 7;
#pragma unroll
        for (int j = 0; j < 4; j++) {
            int jj = j0 + j;
            int jh = jj >> 3, jw = jj & 7;
            int ridx = (ih - jh + 7) * 15 + (iw - jw + 7);
            S[ii * 65 + jj] = s[i][j] + bias_table[ridx * 8 + h] + mrow[ii * 64 + jj];
        }
    }
    __syncthreads();

    // row max
    if (t < 64) {
        float mx = S[t * 65];
        for (int j = 1; j < 64; j++) mx = fmaxf(mx, S[t * 65 + j]);
        rowmax[t] = mx;
    }
    __syncthreads();

    // exp in place
#pragma unroll
    for (int i = 0; i < 4; i++) {
        float mx = rowmax[i0 + i];
#pragma unroll
        for (int j = 0; j < 4; j++) {
            int idx = (i0 + i) * 65 + (j0 + j);
            S[idx] = __expf(S[idx] - mx);
        }
    }
    __syncthreads();

    // row sum
    if (t < 64) {
        float ssum = 0.f;
        for (int j = 0; j < 64; j++) ssum += S[t * 65 + j];
        rowinv[t] = 1.0f / ssum;
    }
    __syncthreads();

    // O = P . V : thread handles (row oi, 8 d's)
    const int oi = t >> 2;
    const int d0 = (t & 3) << 3;
    float o[8];
#pragma unroll
    for (int dd = 0; dd < 8; dd++) o[dd] = 0.f;

    for (int j = 0; j < 64; j++) {
        float p = S[oi * 65 + j];
        float4 va = *(const float4*)&vs[j * 32 + d0];
        float4 vb = *(const float4*)&vs[j * 32 + d0 + 4];
        o[0] = fmaf(p, va.x, o[0]);
        o[1] = fmaf(p, va.y, o[1]);
        o[2] = fmaf(p, va.z, o[2]);
        o[3] = fmaf(p, va.w, o[3]);
        o[4] = fmaf(p, vb.x, o[4]);
        o[5] = fmaf(p, vb.y, o[5]);
        o[6] = fmaf(p, vb.z, o[6]);
        o[7] = fmaf(p, vb.w, o[7]);
    }
    float inv = rowinv[oi];
    float* og = g_o + ((size_t)(b * 64 + oi)) * CDIM + h * 32 + d0;
#pragma unroll
    for (int dd = 0; dd < 8; dd++) og[dd] = o[dd] * inv;
}

// ---------------- launch ----------------
extern "C" void kernel_launch(void* const* d_in, const int* in_sizes, int n_in,
                              void* d_out, int out_size)
{
    const float* x          = (const float*)d_in[0];
    const float* mask       = (const float*)d_in[1];
    const float* Wq         = (const float*)d_in[2];
    const float* bq         = (const float*)d_in[3];
    const float* Wkv        = (const float*)d_in[4];
    const float* bkv        = (const float*)d_in[5];
    const float* bias_table = (const float*)d_in[6];
    const float* Wp         = (const float*)d_in[7];
    const float* bp         = (const float*)d_in[8];
    float* out = (float*)d_out;

    // 1) fused QKV projection -> g_q (scaled), g_k, g_v
    gemm_kernel<0><<<dim3(MROWS / 128, 12), 256>>>(x, Wq, bq, Wkv, bkv, nullptr);
    // 2) per-(window, head) attention -> g_o
    attn_kernel<<<BWIN * HEADS, 256>>>(mask, bias_table);
    // 3) output projection -> d_out
    gemm_kernel<1><<<dim3(MROWS / 128, 4), 256>>>(x, Wp, bp, nullptr, nullptr, out);
}

// round 2
// speedup vs baseline: 1.2635x; 1.2635x over previous
#include <cuda_runtime.h>
#include <cstddef>
#include <cstdint>

// ---------------- problem constants ----------------
constexpr int BWIN = 4096;
constexpr int NTOK = 64;
constexpr int CDIM = 256;
constexpr int HEADS = 8;
constexpr int DHEAD = 32;
constexpr int MROWS = BWIN * NTOK;          // 262144
constexpr float SCALE = 0.1767766952966369f; // 32^-0.5

// ---------------- scratch ----------------
__device__ float g_q[BWIN * HEADS * NTOK * DHEAD];
__device__ float g_k[BWIN * HEADS * NTOK * DHEAD];
__device__ float g_v[BWIN * HEADS * NTOK * DHEAD];
__device__ float g_o[MROWS * CDIM];

// ---------------- helpers ----------------
__device__ __forceinline__ float to_tf32(float x) {
    unsigned r;
    asm("cvt.rna.tf32.f32 %0, %1;" : "=r"(r) : "f"(x));
    return __uint_as_float(r);
}
__device__ __forceinline__ unsigned f2u(float x) { return __float_as_uint(x); }

__device__ __forceinline__ void mma_tf32(float* c, const unsigned* a, const unsigned* b) {
    asm volatile(
        "mma.sync.aligned.m16n8k8.row.col.f32.tf32.tf32.f32 "
        "{%0,%1,%2,%3}, {%4,%5,%6,%7}, {%8,%9}, {%0,%1,%2,%3};"
        : "+f"(c[0]), "+f"(c[1]), "+f"(c[2]), "+f"(c[3])
        : "r"(a[0]), "r"(a[1]), "r"(a[2]), "r"(a[3]), "r"(b[0]), "r"(b[1]));
}

// ---------------- TF32 tensor GEMM: out[m,c] = A[m,:] . W[c,:] + b[c] ----------------
// Tile: BM=128, BN=64, BK=16, 256 threads (8 warps, 4x2), warp tile 32x32.
// MODE 0: A=x, cols [0,256)->g_q (scaled), [256,512)->g_k, [512,768)->g_v
// MODE 1: A=g_o, W=Wp -> outP
template <int MODE>
__global__ void __launch_bounds__(256) mma_gemm(
    const float* __restrict__ A_in,
    const float* __restrict__ W0, const float* __restrict__ b0,
    const float* __restrict__ W1, const float* __restrict__ b1,
    float* __restrict__ outP)
{
    constexpr int BK = 16;
    __shared__ float As[2][BK][136];   // [k][m], pad->136: conflict-free frag loads
    __shared__ float Bs[2][BK][72];    // [k][n], pad->72

    const float* A = (MODE == 0) ? A_in : g_o;
    const int m0 = blockIdx.x * 128;
    const int c0 = blockIdx.y * 64;

    const float* Wsrc;
    const float* bsrc;
    int crow0;
    if (MODE == 1) { Wsrc = W0; bsrc = b0; crow0 = c0; }
    else if (c0 < 256) { Wsrc = W0; bsrc = b0; crow0 = c0; }
    else { Wsrc = W1; bsrc = b1; crow0 = c0 - 256; }

    const int t = threadIdx.x;
    const int wid = t >> 5, lane = t & 31;
    const int wm = wid & 3, wn = wid >> 2;
    const int gid = lane >> 2, tig = lane & 3;
    const int mrow = wm * 32, ncol = wn * 32;

    float c[2][4][4];
#pragma unroll
    for (int mt = 0; mt < 2; mt++)
#pragma unroll
        for (int nt = 0; nt < 4; nt++)
#pragma unroll
            for (int i = 0; i < 4; i++) c[mt][nt][i] = 0.f;

    // staging index maps
    const int arow0 = t >> 2,          akq0 = (t & 3) << 2;         // idx = t
    const int arow1 = (t + 256) >> 2,  akq1 = ((t + 256) & 3) << 2; // idx = t+256
    const int brow  = t >> 2,          bkq  = (t & 3) << 2;

    float4 sa0, sa1, sb;

    auto ldg = [&](int kt) {
        int k0 = kt * BK;
        sa0 = *(const float4*)(A + (size_t)(m0 + arow0) * CDIM + k0 + akq0);
        sa1 = *(const float4*)(A + (size_t)(m0 + arow1) * CDIM + k0 + akq1);
        sb  = *(const float4*)(Wsrc + (size_t)(crow0 + brow) * CDIM + k0 + bkq);
    };
    auto sts = [&](int buf) {
        float va0[4] = {to_tf32(sa0.x), to_tf32(sa0.y), to_tf32(sa0.z), to_tf32(sa0.w)};
        float va1[4] = {to_tf32(sa1.x), to_tf32(sa1.y), to_tf32(sa1.z), to_tf32(sa1.w)};
        float vb[4]  = {to_tf32(sb.x),  to_tf32(sb.y),  to_tf32(sb.z),  to_tf32(sb.w)};
#pragma unroll
        for (int s = 0; s < 4; s++) {  // rotated stores -> no STS bank conflicts
            int j0 = (s + arow0) & 3;  As[buf][akq0 + j0][arow0] = va0[j0];
            int j1 = (s + arow1) & 3;  As[buf][akq1 + j1][arow1] = va1[j1];
            int jb = (s + brow) & 3;   Bs[buf][bkq + jb][brow]   = vb[jb];
        }
    };
    auto compute = [&](int buf) {
#pragma unroll
        for (int k8 = 0; k8 < BK; k8 += 8) {
            unsigned Af[2][4], Bf[4][2];
#pragma unroll
            for (int mt = 0; mt < 2; mt++) {
                int mb = mrow + mt * 16 + gid;
                Af[mt][0] = f2u(As[buf][k8 + tig][mb]);
                Af[mt][1] = f2u(As[buf][k8 + tig][mb + 8]);
                Af[mt][2] = f2u(As[buf][k8 + tig + 4][mb]);
                Af[mt][3] = f2u(As[buf][k8 + tig + 4][mb + 8]);
            }
#pragma unroll
            for (int nt = 0; nt < 4; nt++) {
                int nb = ncol + nt * 8 + gid;
                Bf[nt][0] = f2u(Bs[buf][k8 + tig][nb]);
                Bf[nt][1] = f2u(Bs[buf][k8 + tig + 4][nb]);
            }
#pragma unroll
            for (int mt = 0; mt < 2; mt++)
#pragma unroll
                for (int nt = 0; nt < 4; nt++)
                    mma_tf32(c[mt][nt], Af[mt], Bf[nt]);
        }
    };

    ldg(0);
    sts(0);
    __syncthreads();
#pragma unroll 1
    for (int kt = 0; kt < 16; kt++) {
        int cur = kt & 1;
        if (kt < 15) ldg(kt + 1);
        compute(cur);
        if (kt < 15) sts(cur ^ 1);
        __syncthreads();
    }

    // ---------------- epilogue ----------------
#pragma unroll
    for (int mt = 0; mt < 2; mt++) {
#pragma unroll
        for (int nt = 0; nt < 4; nt++) {
            int clocal = ncol + nt * 8 + 2 * tig;
            float bias0 = bsrc[crow0 + clocal];
            float bias1 = bsrc[crow0 + clocal + 1];
#pragma unroll
            for (int rr = 0; rr < 2; rr++) {
                int row = m0 + mrow + mt * 16 + gid + rr * 8;
                float v0 = c[mt][nt][rr * 2 + 0] + bias0;
                float v1 = c[mt][nt][rr * 2 + 1] + bias1;
                if (MODE == 1) {
                    float2* p = (float2*)(outP + (size_t)row * CDIM + c0 + clocal);
                    *p = make_float2(v0, v1);
                } else {
                    int cg = c0 + clocal;
                    int b = row >> 6, n = row & 63;
                    float* base;
                    if (cg < 256) { base = g_q; v0 *= SCALE; v1 *= SCALE; }
                    else if (cg < 512) { base = g_k; cg -= 256; }
                    else { base = g_v; cg -= 512; }
                    int hh = cg >> 5, dd = cg & 31;
                    float2* p = (float2*)(base + (((size_t)(b * 8 + hh)) * 64 + n) * 32 + dd);
                    *p = make_float2(v0, v1);
                }
            }
        }
    }
}

// ---------------- fused attention per (window, head) ----------------
__global__ void __launch_bounds__(256) attn_kernel(
    const float* __restrict__ mask,
    const float* __restrict__ bias_table)
{
    const int bh = blockIdx.x;
    const int b  = bh >> 3;
    const int h  = bh & 7;

    __shared__ float qs_t[32 * 64];
    __shared__ float ks_t[32 * 64];
    __shared__ float vs[64 * 32];
    __shared__ float S[64 * 65];
    __shared__ float rowmax[64];
    __shared__ float rowinv[64];

    const int t = threadIdx.x;
    const float* qg = g_q + (size_t)bh * 2048;
    const float* kg = g_k + (size_t)bh * 2048;
    const float* vg = g_v + (size_t)bh * 2048;

#pragma unroll
    for (int it = 0; it < 2; it++) {
        int e = (t + it * 256) * 4;
        int n = e >> 5;
        int d = e & 31;
        float4 vq = *(const float4*)&qg[e];
        float4 vk = *(const float4*)&kg[e];
        float4 vv = *(const float4*)&vg[e];
        qs_t[(d + 0) * 64 + n] = vq.x;
        qs_t[(d + 1) * 64 + n] = vq.y;
        qs_t[(d + 2) * 64 + n] = vq.z;
        qs_t[(d + 3) * 64 + n] = vq.w;
        ks_t[(d + 0) * 64 + n] = vk.x;
        ks_t[(d + 1) * 64 + n] = vk.y;
        ks_t[(d + 2) * 64 + n] = vk.z;
        ks_t[(d + 3) * 64 + n] = vk.w;
        *(float4*)&vs[e] = vv;
    }
    __syncthreads();

    const int i0 = (t >> 4) << 2;
    const int j0 = (t & 15) << 2;
    float s[4][4];
#pragma unroll
    for (int i = 0; i < 4; i++)
#pragma unroll
        for (int j = 0; j < 4; j++) s[i][j] = 0.f;

#pragma unroll
    for (int d = 0; d < 32; d++) {
        float qr[4], kr[4];
        *(float4*)qr = *(const float4*)&qs_t[d * 64 + i0];
        *(float4*)kr = *(const float4*)&ks_t[d * 64 + j0];
#pragma unroll
        for (int i = 0; i < 4; i++)
#pragma unroll
            for (int j = 0; j < 4; j++)
                s[i][j] = fmaf(qr[i], kr[j], s[i][j]);
    }

    const int w = b & 1023;
    const float* mrow = mask + (size_t)w * 4096;
#pragma unroll
    for (int i = 0; i < 4; i++) {
        int ii = i0 + i;
        int ih = ii >> 3, iw = ii & 7;
#pragma unroll
        for (int j = 0; j < 4; j++) {
            int jj = j0 + j;
            int jh = jj >> 3, jw = jj & 7;
            int ridx = (ih - jh + 7) * 15 + (iw - jw + 7);
            S[ii * 65 + jj] = s[i][j] + bias_table[ridx * 8 + h] + mrow[ii * 64 + jj];
        }
    }
    __syncthreads();

    if (t < 64) {
        float mx = S[t * 65];
        for (int j = 1; j < 64; j++) mx = fmaxf(mx, S[t * 65 + j]);
        rowmax[t] = mx;
    }
    __syncthreads();

#pragma unroll
    for (int i = 0; i < 4; i++) {
        float mx = rowmax[i0 + i];
#pragma unroll
        for (int j = 0; j < 4; j++) {
            int idx = (i0 + i) * 65 + (j0 + j);
            S[idx] = __expf(S[idx] - mx);
        }
    }
    __syncthreads();

    if (t < 64) {
        float ssum = 0.f;
        for (int j = 0; j < 64; j++) ssum += S[t * 65 + j];
        rowinv[t] = 1.0f / ssum;
    }
    __syncthreads();

    const int oi = t >> 2;
    const int d0 = (t & 3) << 3;
    float o[8];
#pragma unroll
    for (int dd = 0; dd < 8; dd++) o[dd] = 0.f;

    for (int j = 0; j < 64; j++) {
        float p = S[oi * 65 + j];
        float4 va = *(const float4*)&vs[j * 32 + d0];
        float4 vb = *(const float4*)&vs[j * 32 + d0 + 4];
        o[0] = fmaf(p, va.x, o[0]);
        o[1] = fmaf(p, va.y, o[1]);
        o[2] = fmaf(p, va.z, o[2]);
        o[3] = fmaf(p, va.w, o[3]);
        o[4] = fmaf(p, vb.x, o[4]);
        o[5] = fmaf(p, vb.y, o[5]);
        o[6] = fmaf(p, vb.z, o[6]);
        o[7] = fmaf(p, vb.w, o[7]);
    }
    float inv = rowinv[oi];
    float* og = g_o + ((size_t)(b * 64 + oi)) * CDIM + h * 32 + d0;
#pragma unroll
    for (int dd = 0; dd < 8; dd++) og[dd] = o[dd] * inv;
}

// ---------------- launch ----------------
extern "C" void kernel_launch(void* const* d_in, const int* in_sizes, int n_in,
                              void* d_out, int out_size)
{
    const float* x          = (const float*)d_in[0];
    const float* mask       = (const float*)d_in[1];
    const float* Wq         = (const float*)d_in[2];
    const float* bq         = (const float*)d_in[3];
    const float* Wkv        = (const float*)d_in[4];
    const float* bkv        = (const float*)d_in[5];
    const float* bias_table = (const float*)d_in[6];
    const float* Wp         = (const float*)d_in[7];
    const float* bp         = (const float*)d_in[8];
    float* out = (float*)d_out;

    mma_gemm<0><<<dim3(MROWS / 128, 12), 256>>>(x, Wq, bq, Wkv, bkv, nullptr);
    attn_kernel<<<BWIN * HEADS, 256>>>(mask, bias_table);
    mma_gemm<1><<<dim3(MROWS / 128, 4), 256>>>(x, Wp, bp, nullptr, nullptr, out);
}

// round 3
// speedup vs baseline: 1.7473x; 1.3829x over previous
#include <cuda_runtime.h>
#include <cstddef>
#include <cstdint>

// ---------------- problem constants ----------------
constexpr int BWIN = 4096;
constexpr int NTOK = 64;
constexpr int CDIM = 256;
constexpr int HEADS = 8;
constexpr int DHEAD = 32;
constexpr int MROWS = BWIN * NTOK;          // 262144
constexpr float SCALE = 0.1767766952966369f; // 32^-0.5

// ---------------- scratch ----------------
__device__ float g_q[BWIN * HEADS * NTOK * DHEAD];
__device__ float g_k[BWIN * HEADS * NTOK * DHEAD];
__device__ float g_v[BWIN * HEADS * NTOK * DHEAD];
__device__ float g_o[MROWS * CDIM];

// ---------------- helpers ----------------
__device__ __forceinline__ float to_tf32(float x) {
    unsigned r;
    asm("cvt.rna.tf32.f32 %0, %1;" : "=r"(r) : "f"(x));
    return __uint_as_float(r);
}
__device__ __forceinline__ unsigned f2u(float x) { return __float_as_uint(x); }

__device__ __forceinline__ void mma_tf32(float* c, unsigned a0, unsigned a1,
                                         unsigned a2, unsigned a3,
                                         unsigned b0, unsigned b1) {
    asm volatile(
        "mma.sync.aligned.m16n8k8.row.col.f32.tf32.tf32.f32 "
        "{%0,%1,%2,%3}, {%4,%5,%6,%7}, {%8,%9}, {%0,%1,%2,%3};"
        : "+f"(c[0]), "+f"(c[1]), "+f"(c[2]), "+f"(c[3])
        : "r"(a0), "r"(a1), "r"(a2), "r"(a3), "r"(b0), "r"(b1));
}

// ---------------- TF32 tensor GEMM: out[m,c] = A[m,:] . W[c,:] + b[c] ----------------
// BM=128, BN=64, BK=16; 8 warps (4x2), warp tile 32x32 (2x4 m16n8k8 frags).
// SMEM layout: [row][kperm], kperm=(k&3)*4+(k>>2), chunk swizzle ^((row>>1)&3).
//   -> frag loads are LDS.128, STS/LDS both bank-conflict-free, no padding.
// MODE 0: A=x, cols [0,256)->g_q (scaled), [256,512)->g_k, [512,768)->g_v
// MODE 1: A=g_o, W=Wp -> outP
template <int MODE>
__global__ void __launch_bounds__(256) mma_gemm(
    const float* __restrict__ A_in,
    const float* __restrict__ W0, const float* __restrict__ b0,
    const float* __restrict__ W1, const float* __restrict__ b1,
    float* __restrict__ outP)
{
    __shared__ float As[2][128 * 16];
    __shared__ float Bs[2][64 * 16];

    const float* A = (MODE == 0) ? A_in : g_o;
    const int m0 = blockIdx.x * 128;
    const int c0 = blockIdx.y * 64;

    const float* Wsrc;
    const float* bsrc;
    int crow0;
    if (MODE == 1) { Wsrc = W0; bsrc = b0; crow0 = c0; }
    else if (c0 < 256) { Wsrc = W0; bsrc = b0; crow0 = c0; }
    else { Wsrc = W1; bsrc = b1; crow0 = c0 - 256; }

    const int t = threadIdx.x;
    const int wid = t >> 5, lane = t & 31;
    const int wm = wid & 3, wn = wid >> 2;
    const int gid = lane >> 2, tig = lane & 3;
    const int mrow = wm * 32, ncol = wn * 32;

    float c[2][4][4];
#pragma unroll
    for (int mt = 0; mt < 2; mt++)
#pragma unroll
        for (int nt = 0; nt < 4; nt++)
#pragma unroll
            for (int i = 0; i < 4; i++) c[mt][nt][i] = 0.f;

    // ---- staging maps (row, q = offset-in-chunk; global k = 4q+j) ----
    const int srow = t >> 2;           // 0..63
    const int q = t & 3;
    int aoff0[4], aoff1[4];            // A rows srow and srow+64; B rows = srow
#pragma unroll
    for (int j = 0; j < 4; j++) {
        aoff0[j] = srow * 16 + ((j ^ ((srow >> 1) & 3)) << 2) + q;
        int r1 = srow + 64;
        aoff1[j] = r1 * 16 + ((j ^ ((r1 >> 1) & 3)) << 2) + q;
    }

    // ---- fragment load addresses (float4 index) ----
    int aAddr[2][2], bAddr[4];
#pragma unroll
    for (int mt = 0; mt < 2; mt++) {
        int r0 = mrow + mt * 16 + gid;
        int r1 = r0 + 8;
        aAddr[mt][0] = r0 * 16 + ((tig ^ ((r0 >> 1) & 3)) << 2);
        aAddr[mt][1] = r1 * 16 + ((tig ^ ((r1 >> 1) & 3)) << 2);
    }
#pragma unroll
    for (int nt = 0; nt < 4; nt++) {
        int nb = ncol + nt * 8 + gid;
        bAddr[nt] = nb * 16 + ((tig ^ ((nb >> 1) & 3)) << 2);
    }

    float4 sa0, sa1, sb;
    auto ldg = [&](int kt) {
        int k0 = kt * 16 + q * 4;
        sa0 = *(const float4*)(A + (size_t)(m0 + srow) * CDIM + k0);
        sa1 = *(const float4*)(A + (size_t)(m0 + srow + 64) * CDIM + k0);
        sb  = *(const float4*)(Wsrc + (size_t)(crow0 + srow) * CDIM + k0);
    };

    ldg(0);
    {
        float* as = As[0]; float* bs = Bs[0];
        float va0[4] = {to_tf32(sa0.x), to_tf32(sa0.y), to_tf32(sa0.z), to_tf32(sa0.w)};
        float va1[4] = {to_tf32(sa1.x), to_tf32(sa1.y), to_tf32(sa1.z), to_tf32(sa1.w)};
        float vb[4]  = {to_tf32(sb.x),  to_tf32(sb.y),  to_tf32(sb.z),  to_tf32(sb.w)};
#pragma unroll
        for (int j = 0; j < 4; j++) {
            as[aoff0[j]] = va0[j];
            as[aoff1[j]] = va1[j];
            bs[aoff0[j]] = vb[j];
        }
    }
    __syncthreads();

#pragma unroll
    for (int kt = 0; kt < 16; kt++) {
        const int cur = kt & 1;
        if (kt < 15) ldg(kt + 1);

        // ---- compute on buffer `cur` (compile-time constant) ----
        {
            const float4* as = (const float4*)As[cur];
            const float4* bs = (const float4*)Bs[cur];
            float4 a4[2][2], b4[4];
#pragma unroll
            for (int mt = 0; mt < 2; mt++) {
                a4[mt][0] = as[aAddr[mt][0] >> 2];
                a4[mt][1] = as[aAddr[mt][1] >> 2];
            }
#pragma unroll
            for (int nt = 0; nt < 4; nt++) b4[nt] = bs[bAddr[nt] >> 2];

            // k8 = 0 : elements .x (k=tig), .y (k=tig+4)
#pragma unroll
            for (int mt = 0; mt < 2; mt++)
#pragma unroll
                for (int nt = 0; nt < 4; nt++)
                    mma_tf32(c[mt][nt],
                             f2u(a4[mt][0].x), f2u(a4[mt][1].x),
                             f2u(a4[mt][0].y), f2u(a4[mt][1].y),
                             f2u(b4[nt].x),    f2u(b4[nt].y));
            // k8 = 1 : elements .z (k=tig+8), .w (k=tig+12)
#pragma unroll
            for (int mt = 0; mt < 2; mt++)
#pragma unroll
                for (int nt = 0; nt < 4; nt++)
                    mma_tf32(c[mt][nt],
                             f2u(a4[mt][0].z), f2u(a4[mt][1].z),
                             f2u(a4[mt][0].w), f2u(a4[mt][1].w),
                             f2u(b4[nt].z),    f2u(b4[nt].w));
        }

        if (kt < 15) {
            float* as = As[cur ^ 1]; float* bs = Bs[cur ^ 1];
            float va0[4] = {to_tf32(sa0.x), to_tf32(sa0.y), to_tf32(sa0.z), to_tf32(sa0.w)};
            float va1[4] = {to_tf32(sa1.x), to_tf32(sa1.y), to_tf32(sa1.z), to_tf32(sa1.w)};
            float vb[4]  = {to_tf32(sb.x),  to_tf32(sb.y),  to_tf32(sb.z),  to_tf32(sb.w)};
#pragma unroll
            for (int j = 0; j < 4; j++) {
                as[aoff0[j]] = va0[j];
                as[aoff1[j]] = va1[j];
                bs[aoff0[j]] = vb[j];
            }
        }
        __syncthreads();
    }

    // ---------------- epilogue ----------------
#pragma unroll
    for (int mt = 0; mt < 2; mt++) {
#pragma unroll
        for (int nt = 0; nt < 4; nt++) {
            int clocal = ncol + nt * 8 + 2 * tig;
            float bias0 = bsrc[crow0 + clocal];
            float bias1 = bsrc[crow0 + clocal + 1];
#pragma unroll
            for (int rr = 0; rr < 2; rr++) {
                int row = m0 + mrow + mt * 16 + gid + rr * 8;
                float v0 = c[mt][nt][rr * 2 + 0] + bias0;
                float v1 = c[mt][nt][rr * 2 + 1] + bias1;
                if (MODE == 1) {
                    float2* p = (float2*)(outP + (size_t)row * CDIM + c0 + clocal);
                    *p = make_float2(v0, v1);
                } else {
                    int cg = c0 + clocal;
                    int b = row >> 6, n = row & 63;
                    float* base;
                    if (cg < 256) { base = g_q; v0 *= SCALE; v1 *= SCALE; }
                    else if (cg < 512) { base = g_k; cg -= 256; }
                    else { base = g_v; cg -= 512; }
                    int hh = cg >> 5, dd = cg & 31;
                    float2* p = (float2*)(base + (((size_t)(b * 8 + hh)) * 64 + n) * 32 + dd);
                    *p = make_float2(v0, v1);
                }
            }
        }
    }
}

// ---------------- fused attention per (window, head) ----------------
__global__ void __launch_bounds__(256) attn_kernel(
    const float* __restrict__ mask,
    const float* __restrict__ bias_table)
{
    const int bh = blockIdx.x;
    const int b  = bh >> 3;
    const int h  = bh & 7;

    __shared__ float qs_t[32 * 64];
    __shared__ float ks_t[32 * 64];
    __shared__ float vs[64 * 32];
    __shared__ float S[64 * 65];
    __shared__ float rowmax[64];
    __shared__ float rowinv[64];

    const int t = threadIdx.x;
    const float* qg = g_q + (size_t)bh * 2048;
    const float* kg = g_k + (size_t)bh * 2048;
    const float* vg = g_v + (size_t)bh * 2048;

#pragma unroll
    for (int it = 0; it < 2; it++) {
        int e = (t + it * 256) * 4;
        int n = e >> 5;
        int d = e & 31;
        float4 vq = *(const float4*)&qg[e];
        float4 vk = *(const float4*)&kg[e];
        float4 vv = *(const float4*)&vg[e];
        qs_t[(d + 0) * 64 + n] = vq.x;
        qs_t[(d + 1) * 64 + n] = vq.y;
        qs_t[(d + 2) * 64 + n] = vq.z;
        qs_t[(d + 3) * 64 + n] = vq.w;
        ks_t[(d + 0) * 64 + n] = vk.x;
        ks_t[(d + 1) * 64 + n] = vk.y;
        ks_t[(d + 2) * 64 + n] = vk.z;
        ks_t[(d + 3) * 64 + n] = vk.w;
        *(float4*)&vs[e] = vv;
    }
    __syncthreads();

    const int i0 = (t >> 4) << 2;
    const int j0 = (t & 15) << 2;
    float s[4][4];
#pragma unroll
    for (int i = 0; i < 4; i++)
#pragma unroll
        for (int j = 0; j < 4; j++) s[i][j] = 0.f;

#pragma unroll
    for (int d = 0; d < 32; d++) {
        float qr[4], kr[4];
        *(float4*)qr = *(const float4*)&qs_t[d * 64 + i0];
        *(float4*)kr = *(const float4*)&ks_t[d * 64 + j0];
#pragma unroll
        for (int i = 0; i < 4; i++)
#pragma unroll
            for (int j = 0; j < 4; j++)
                s[i][j] = fmaf(qr[i], kr[j], s[i][j]);
    }

    const int w = b & 1023;
    const float* mrow = mask + (size_t)w * 4096;
#pragma unroll
    for (int i = 0; i < 4; i++) {
        int ii = i0 + i;
        int ih = ii >> 3, iw = ii & 7;
#pragma unroll
        for (int j = 0; j < 4; j++) {
            int jj = j0 + j;
            int jh = jj >> 3, jw = jj & 7;
            int ridx = (ih - jh + 7) * 15 + (iw - jw + 7);
            S[ii * 65 + jj] = s[i][j] + bias_table[ridx * 8 + h] + mrow[ii * 64 + jj];
        }
    }
    __syncthreads();

    if (t < 64) {
        float mx = S[t * 65];
        for (int j = 1; j < 64; j++) mx = fmaxf(mx, S[t * 65 + j]);
        rowmax[t] = mx;
    }
    __syncthreads();

#pragma unroll
    for (int i = 0; i < 4; i++) {
        float mx = rowmax[i0 + i];
#pragma unroll
        for (int j = 0; j < 4; j++) {
            int idx = (i0 + i) * 65 + (j0 + j);
            S[idx] = __expf(S[idx] - mx);
        }
    }
    __syncthreads();

    if (t < 64) {
        float ssum = 0.f;
        for (int j = 0; j < 64; j++) ssum += S[t * 65 + j];
        rowinv[t] = 1.0f / ssum;
    }
    __syncthreads();

    const int oi = t >> 2;
    const int d0 = (t & 3) << 3;
    float o[8];
#pragma unroll
    for (int dd = 0; dd < 8; dd++) o[dd] = 0.f;

    for (int j = 0; j < 64; j++) {
        float p = S[oi * 65 + j];
        float4 va = *(const float4*)&vs[j * 32 + d0];
        float4 vb = *(const float4*)&vs[j * 32 + d0 + 4];
        o[0] = fmaf(p, va.x, o[0]);
        o[1] = fmaf(p, va.y, o[1]);
        o[2] = fmaf(p, va.z, o[2]);
        o[3] = fmaf(p, va.w, o[3]);
        o[4] = fmaf(p, vb.x, o[4]);
        o[5] = fmaf(p, vb.y, o[5]);
        o[6] = fmaf(p, vb.z, o[6]);
        o[7] = fmaf(p, vb.w, o[7]);
    }
    float inv = rowinv[oi];
    float* og = g_o + ((size_t)(b * 64 + oi)) * CDIM + h * 32 + d0;
#pragma unroll
    for (int dd = 0; dd < 8; dd++) og[dd] = o[dd] * inv;
}

// ---------------- launch ----------------
extern "C" void kernel_launch(void* const* d_in, const int* in_sizes, int n_in,
                              void* d_out, int out_size)
{
    const float* x          = (const float*)d_in[0];
    const float* mask       = (const float*)d_in[1];
    const float* Wq         = (const float*)d_in[2];
    const float* bq         = (const float*)d_in[3];
    const float* Wkv        = (const float*)d_in[4];
    const float* bkv        = (const float*)d_in[5];
    const float* bias_table = (const float*)d_in[6];
    const float* Wp         = (const float*)d_in[7];
    const float* bp         = (const float*)d_in[8];
    float* out = (float*)d_out;

    mma_gemm<0><<<dim3(MROWS / 128, 12), 256>>>(x, Wq, bq, Wkv, bkv, nullptr);
    attn_kernel<<<BWIN * HEADS, 256>>>(mask, bias_table);
    mma_gemm<1><<<dim3(MROWS / 128, 4), 256>>>(x, Wp, bp, nullptr, nullptr, out);
}

// round 4
// speedup vs baseline: 2.0632x; 1.1808x over previous
#include <cuda_runtime.h>
#include <cstddef>
#include <cstdint>

// ---------------- problem constants ----------------
constexpr int BWIN = 4096;
constexpr int NTOK = 64;
constexpr int CDIM = 256;
constexpr int HEADS = 8;
constexpr int DHEAD = 32;
constexpr int MROWS = BWIN * NTOK;          // 262144
constexpr float SCALE = 0.1767766952966369f; // 32^-0.5

// ---------------- scratch ----------------
__device__ float g_q[BWIN * HEADS * NTOK * DHEAD];
__device__ float g_k[BWIN * HEADS * NTOK * DHEAD];
__device__ float g_v[BWIN * HEADS * NTOK * DHEAD];
__device__ float g_o[MROWS * CDIM];     // permuted tf32 (A of proj GEMM)
__device__ float g_xt[MROWS * CDIM];    // permuted tf32 x
__device__ float g_wt[1024 * CDIM];     // permuted tf32 weights: [0,256)=Wq, [256,768)=Wkv, [768,1024)=Wp

// ---------------- helpers ----------------
__device__ __forceinline__ float to_tf32(float x) {
    unsigned r;
    asm("cvt.rna.tf32.f32 %0, %1;" : "=r"(r) : "f"(x));
    return __uint_as_float(r);
}
__device__ __forceinline__ unsigned f2u(float x) { return __float_as_uint(x); }

__device__ __forceinline__ void mma_tf32(float* c, unsigned a0, unsigned a1,
                                         unsigned a2, unsigned a3,
                                         unsigned b0, unsigned b1) {
    asm volatile(
        "mma.sync.aligned.m16n8k8.row.col.f32.tf32.tf32.f32 "
        "{%0,%1,%2,%3}, {%4,%5,%6,%7}, {%8,%9}, {%0,%1,%2,%3};"
        : "+f"(c[0]), "+f"(c[1]), "+f"(c[2]), "+f"(c[3])
        : "r"(a0), "r"(a1), "r"(a2), "r"(a3), "r"(b0), "r"(b1));
}

__device__ __forceinline__ void cp16(uint32_t dst, const void* src) {
    asm volatile("cp.async.cg.shared.global [%0], [%1], 16;" :: "r"(dst), "l"(src) : "memory");
}
__device__ __forceinline__ void cp_commit() {
    asm volatile("cp.async.commit_group;" ::: "memory");
}
__device__ __forceinline__ void cp_wait2() {
    asm volatile("cp.async.wait_group 2;" ::: "memory");
}

// ---------------- permute + tf32 round ----------------
// dst[row*256 + 16g + 4c + q] = tf32(src[row*256 + 16g + 4q + c])
__global__ void __launch_bounds__(256) permute_tf32(
    const float* __restrict__ src, float* __restrict__ dst, int ngroups)
{
    int g = blockIdx.x * 256 + threadIdx.x;
    if (g >= ngroups) return;
    const float4* s = (const float4*)src + (size_t)g * 4;
    float4 v0 = s[0], v1 = s[1], v2 = s[2], v3 = s[3];
    float4* d = (float4*)dst + (size_t)g * 4;
    d[0] = make_float4(to_tf32(v0.x), to_tf32(v1.x), to_tf32(v2.x), to_tf32(v3.x));
    d[1] = make_float4(to_tf32(v0.y), to_tf32(v1.y), to_tf32(v2.y), to_tf32(v3.y));
    d[2] = make_float4(to_tf32(v0.z), to_tf32(v1.z), to_tf32(v2.z), to_tf32(v3.z));
    d[3] = make_float4(to_tf32(v0.w), to_tf32(v1.w), to_tf32(v2.w), to_tf32(v3.w));
}

// ---------------- TF32 tensor GEMM, cp.async pipelined ----------------
// out[m,c] = A[m,:] . W[c,:] + b[c];  A,W pre-permuted tf32.
// BM=128, BN=64, BK=16, 4 stages; 8 warps (4x2), warp tile 32x32.
// MODE 0: A=g_xt, W rows 0..767 of g_wt; cols->g_q(scaled)/g_k/g_v scatter.
// MODE 1: A=g_o,  W rows 768..1023 of g_wt -> outP.
template <int MODE>
__global__ void __launch_bounds__(256, 2) mma_gemm(
    const float* __restrict__ b0v, const float* __restrict__ b1v,
    float* __restrict__ outP)
{
    constexpr int STAGES = 4;
    __shared__ float4 As4[STAGES][128 * 4];
    __shared__ float4 Bs4[STAGES][64 * 4];

    const float* A = (MODE == 0) ? g_xt : g_o;
    const int c0 = blockIdx.x * 64;                // c-tile fastest -> A cached in L2
    const int m0 = blockIdx.y * 128;
    const float* Wsrc = g_wt + (MODE == 0 ? 0 : 768 * CDIM);

    const int t = threadIdx.x;
    const int wid = t >> 5, lane = t & 31;
    const int wm = wid & 3, wn = wid >> 2;
    const int gid = lane >> 2, tig = lane & 3;
    const int mrow = wm * 32, ncol = wn * 32;

    float c[2][4][4];
#pragma unroll
    for (int mt = 0; mt < 2; mt++)
#pragma unroll
        for (int nt = 0; nt < 4; nt++)
#pragma unroll
            for (int i = 0; i < 4; i++) c[mt][nt][i] = 0.f;

    // ---- cp.async per-thread mapping ----
    const int arow = t >> 2;       // 0..63
    const int ac = t & 3;          // logical chunk
    const int apc  = ac ^ ((arow >> 1) & 3);
    const int arowB = arow + 64;
    const int apcB = ac ^ ((arowB >> 1) & 3);

    const uint32_t dA0 = (uint32_t)__cvta_generic_to_shared(&As4[0][arow * 4 + apc]);
    const uint32_t dA1 = (uint32_t)__cvta_generic_to_shared(&As4[0][arowB * 4 + apcB]);
    const uint32_t dB  = (uint32_t)__cvta_generic_to_shared(&Bs4[0][arow * 4 + apc]);
    constexpr uint32_t ASTRIDE = 128 * 4 * 16;
    constexpr uint32_t BSTRIDE = 64 * 4 * 16;

    const float* srcA0 = A + (size_t)(m0 + arow) * CDIM + ac * 4;
    const float* srcA1 = A + (size_t)(m0 + arow + 64) * CDIM + ac * 4;
    const float* srcB  = Wsrc + (size_t)(c0 + arow) * CDIM + ac * 4;

    auto issue = [&](int kt, int s) {
        cp16(dA0 + s * ASTRIDE, srcA0 + kt * 16);
        cp16(dA1 + s * ASTRIDE, srcA1 + kt * 16);
        cp16(dB  + s * BSTRIDE, srcB  + kt * 16);
    };

    // ---- fragment load indices (float4 units) ----
    int aIdx[2][2], bIdx[4];
#pragma unroll
    for (int mt = 0; mt < 2; mt++) {
        int r0 = mrow + mt * 16 + gid;
        int r1 = r0 + 8;
        aIdx[mt][0] = r0 * 4 + (tig ^ ((r0 >> 1) & 3));
        aIdx[mt][1] = r1 * 4 + (tig ^ ((r1 >> 1) & 3));
    }
#pragma unroll
    for (int nt = 0; nt < 4; nt++) {
        int nb = ncol + nt * 8 + gid;
        bIdx[nt] = nb * 4 + (tig ^ ((nb >> 1) & 3));
    }

    // ---- prologue: stages 0..2 ----
#pragma unroll
    for (int s = 0; s < STAGES - 1; s++) {
        issue(s, s);
        cp_commit();
    }

#pragma unroll
    for (int kt = 0; kt < 16; kt++) {
        const int buf = kt & 3;
        cp_wait2();
        __syncthreads();

        {
            const float4* as = As4[buf];
            const float4* bs = Bs4[buf];
            float4 a4[2][2], b4[4];
#pragma unroll
            for (int mt = 0; mt < 2; mt++) {
                a4[mt][0] = as[aIdx[mt][0]];
                a4[mt][1] = as[aIdx[mt][1]];
            }
#pragma unroll
            for (int nt = 0; nt < 4; nt++) b4[nt] = bs[bIdx[nt]];

#pragma unroll
            for (int mt = 0; mt < 2; mt++)
#pragma unroll
                for (int nt = 0; nt < 4; nt++)
                    mma_tf32(c[mt][nt],
                             f2u(a4[mt][0].x), f2u(a4[mt][1].x),
                             f2u(a4[mt][0].y), f2u(a4[mt][1].y),
                             f2u(b4[nt].x),    f2u(b4[nt].y));
#pragma unroll
            for (int mt = 0; mt < 2; mt++)
#pragma unroll
                for (int nt = 0; nt < 4; nt++)
                    mma_tf32(c[mt][nt],
                             f2u(a4[mt][0].z), f2u(a4[mt][1].z),
                             f2u(a4[mt][0].w), f2u(a4[mt][1].w),
                             f2u(b4[nt].z),    f2u(b4[nt].w));
        }

        if (kt + STAGES - 1 < 16) issue(kt + STAGES - 1, (kt + STAGES - 1) & 3);
        cp_commit();
    }

    // ---------------- epilogue ----------------
#pragma unroll
    for (int mt = 0; mt < 2; mt++) {
#pragma unroll
        for (int nt = 0; nt < 4; nt++) {
            int clocal = ncol + nt * 8 + 2 * tig;
            int cg = c0 + clocal;
            float bias0, bias1;
            if (MODE == 1) { bias0 = b0v[cg]; bias1 = b0v[cg + 1]; }
            else if (cg < 256) { bias0 = b0v[cg]; bias1 = b0v[cg + 1]; }
            else { bias0 = b1v[cg - 256]; bias1 = b1v[cg - 255]; }
#pragma unroll
            for (int rr = 0; rr < 2; rr++) {
                int row = m0 + mrow + mt * 16 + gid + rr * 8;
                float v0 = c[mt][nt][rr * 2 + 0] + bias0;
                float v1 = c[mt][nt][rr * 2 + 1] + bias1;
                if (MODE == 1) {
                    float2* p = (float2*)(outP + (size_t)row * CDIM + cg);
                    *p = make_float2(v0, v1);
                } else {
                    int cc = cg;
                    int b = row >> 6, n = row & 63;
                    float* base;
                    if (cc < 256) { base = g_q; v0 *= SCALE; v1 *= SCALE; }
                    else if (cc < 512) { base = g_k; cc -= 256; }
                    else { base = g_v; cc -= 512; }
                    int hh = cc >> 5, dd = cc & 31;
                    float2* p = (float2*)(base + (((size_t)(b * 8 + hh)) * 64 + n) * 32 + dd);
                    *p = make_float2(v0, v1);
                }
            }
        }
    }
}

// ---------------- fused attention per (window, head) ----------------
__global__ void __launch_bounds__(256) attn_kernel(
    const float* __restrict__ mask,
    const float* __restrict__ bias_table)
{
    const int bh = blockIdx.x;
    const int b  = bh >> 3;
    const int h  = bh & 7;

    __shared__ float qs_t[32 * 64];
    __shared__ float ks_t[32 * 64];
    __shared__ float vs[64 * 32];
    __shared__ float S[64 * 65];
    __shared__ float rowmax[64];
    __shared__ float rowinv[64];

    const int t = threadIdx.x;
    const float* qg = g_q + (size_t)bh * 2048;
    const float* kg = g_k + (size_t)bh * 2048;
    const float* vg = g_v + (size_t)bh * 2048;

#pragma unroll
    for (int it = 0; it < 2; it++) {
        int e = (t + it * 256) * 4;
        int n = e >> 5;
        int d = e & 31;
        float4 vq = *(const float4*)&qg[e];
        float4 vk = *(const float4*)&kg[e];
        float4 vv = *(const float4*)&vg[e];
        qs_t[(d + 0) * 64 + n] = vq.x;
        qs_t[(d + 1) * 64 + n] = vq.y;
        qs_t[(d + 2) * 64 + n] = vq.z;
        qs_t[(d + 3) * 64 + n] = vq.w;
        ks_t[(d + 0) * 64 + n] = vk.x;
        ks_t[(d + 1) * 64 + n] = vk.y;
        ks_t[(d + 2) * 64 + n] = vk.z;
        ks_t[(d + 3) * 64 + n] = vk.w;
        *(float4*)&vs[e] = vv;
    }
    __syncthreads();

    const int i0 = (t >> 4) << 2;
    const int j0 = (t & 15) << 2;
    float s[4][4];
#pragma unroll
    for (int i = 0; i < 4; i++)
#pragma unroll
        for (int j = 0; j < 4; j++) s[i][j] = 0.f;

#pragma unroll
    for (int d = 0; d < 32; d++) {
        float qr[4], kr[4];
        *(float4*)qr = *(const float4*)&qs_t[d * 64 + i0];
        *(float4*)kr = *(const float4*)&ks_t[d * 64 + j0];
#pragma unroll
        for (int i = 0; i < 4; i++)
#pragma unroll
            for (int j = 0; j < 4; j++)
                s[i][j] = fmaf(qr[i], kr[j], s[i][j]);
    }

    const int w = b & 1023;
    const float* mrow = mask + (size_t)w * 4096;
#pragma unroll
    for (int i = 0; i < 4; i++) {
        int ii = i0 + i;
        int ih = ii >> 3, iw = ii & 7;
#pragma unroll
        for (int j = 0; j < 4; j++) {
            int jj = j0 + j;
            int jh = jj >> 3, jw = jj & 7;
            int ridx = (ih - jh + 7) * 15 + (iw - jw + 7);
            S[ii * 65 + jj] = s[i][j] + bias_table[ridx * 8 + h] + mrow[ii * 64 + jj];
        }
    }
    __syncthreads();

    if (t < 64) {
        float mx = S[t * 65];
        for (int j = 1; j < 64; j++) mx = fmaxf(mx, S[t * 65 + j]);
        rowmax[t] = mx;
    }
    __syncthreads();

#pragma unroll
    for (int i = 0; i < 4; i++) {
        float mx = rowmax[i0 + i];
#pragma unroll
        for (int j = 0; j < 4; j++) {
            int idx = (i0 + i) * 65 + (j0 + j);
            S[idx] = __expf(S[idx] - mx);
        }
    }
    __syncthreads();

    if (t < 64) {
        float ssum = 0.f;
        for (int j = 0; j < 64; j++) ssum += S[t * 65 + j];
        rowinv[t] = 1.0f / ssum;
    }
    __syncthreads();

    const int oi = t >> 2;
    const int d0 = (t & 3) << 3;
    float o[8];
#pragma unroll
    for (int dd = 0; dd < 8; dd++) o[dd] = 0.f;

    for (int j = 0; j < 64; j++) {
        float p = S[oi * 65 + j];
        float4 va = *(const float4*)&vs[j * 32 + d0];
        float4 vb = *(const float4*)&vs[j * 32 + d0 + 4];
        o[0] = fmaf(p, va.x, o[0]);
        o[1] = fmaf(p, va.y, o[1]);
        o[2] = fmaf(p, va.z, o[2]);
        o[3] = fmaf(p, va.w, o[3]);
        o[4] = fmaf(p, vb.x, o[4]);
        o[5] = fmaf(p, vb.y, o[5]);
        o[6] = fmaf(p, vb.z, o[6]);
        o[7] = fmaf(p, vb.w, o[7]);
    }
    float inv = rowinv[oi];
    // store permuted + tf32-rounded (A operand of proj GEMM)
    size_t rowoff = ((size_t)(b * 64 + oi)) * CDIM;
    int colbase = h * 32 + d0;
#pragma unroll
    for (int dd = 0; dd < 8; dd++) {
        int col = colbase + dd;
        int p = (col & ~15) | ((col & 3) << 2) | ((col >> 2) & 3);
        g_o[rowoff + p] = to_tf32(o[dd] * inv);
    }
}

// ---------------- launch ----------------
extern "C" void kernel_launch(void* const* d_in, const int* in_sizes, int n_in,
                              void* d_out, int out_size)
{
    const float* x          = (const float*)d_in[0];
    const float* mask       = (const float*)d_in[1];
    const float* Wq         = (const float*)d_in[2];
    const float* bq         = (const float*)d_in[3];
    const float* Wkv        = (const float*)d_in[4];
    const float* bkv        = (const float*)d_in[5];
    const float* bias_table = (const float*)d_in[6];
    const float* Wp         = (const float*)d_in[7];
    const float* bp         = (const float*)d_in[8];
    float* out = (float*)d_out;

    float* wt;
    cudaGetSymbolAddress((void**)&wt, g_wt);
    float* xt;
    cudaGetSymbolAddress((void**)&xt, g_xt);

    // permute + tf32 round operands
    permute_tf32<<<(MROWS * 16 + 255) / 256, 256>>>(x, xt, MROWS * 16);
    permute_tf32<<<(256 * 16 + 255) / 256, 256>>>(Wq, wt, 256 * 16);
    permute_tf32<<<(512 * 16 + 255) / 256, 256>>>(Wkv, wt + 256 * CDIM, 512 * 16);
    permute_tf32<<<(256 * 16 + 255) / 256, 256>>>(Wp, wt + 768 * CDIM, 256 * 16);

    mma_gemm<0><<<dim3(12, MROWS / 128), 256>>>(bq, bkv, nullptr);
    attn_kernel<<<BWIN * HEADS, 256>>>(mask, bias_table);
    mma_gemm<1><<<dim3(4, MROWS / 128), 256>>>(bp, nullptr, out);
}